// round 1
// baseline (speedup 1.0000x reference)
#include <cuda_runtime.h>
#include <math_constants.h>

#define NB 8
#define NPTS 4096
#define KNN 16
#define MPTS (NB * NPTS)
#define CH 32
#define NCLS 40

// scratch (no cudaMalloc allowed)
__device__ int   g_knn[MPTS * KNN];
__device__ float g_x1[MPTS * CH];
__device__ float g_x2[MPTS * CH];
__device__ float g_pool[NB * CH];

__device__ __forceinline__ float safe_norm3(float x, float y, float z) {
    float s = x * x + y * y + z * z;
    return s > 0.f ? sqrtf(s) : 0.f;
}

__device__ __forceinline__ float angle3(float ax, float ay, float az,
                                        float bx, float by, float bz) {
    float cx = ay * bz - az * by;
    float cy = az * bx - ax * bz;
    float cz = ax * by - ay * bx;
    float cn = safe_norm3(cx, cy, cz);
    float d  = ax * bx + ay * by + az * bz;
    bool ok = (cn > 0.f) || (d != 0.f);
    return ok ? atan2f(cn, d) : 0.f;
}

// ---------------------------------------------------------------------------
// kNN: one thread per query point, tile candidates through smem as float4.
// Matches reference d2 = |pi|^2 + |pj|^2 - 2 pi.pj, diagonal excluded,
// top-16 smallest with lower-index tie-break (like lax.top_k on -d2).
// ---------------------------------------------------------------------------
__global__ __launch_bounds__(256) void knn_kernel(const float* __restrict__ pos) {
    int b  = blockIdx.y;
    int qi = blockIdx.x * 256 + threadIdx.x;   // local index within batch
    const float* pb = pos + (size_t)b * NPTS * 3;

    float qx = pb[qi * 3 + 0];
    float qy = pb[qi * 3 + 1];
    float qz = pb[qi * 3 + 2];
    float qs = qx * qx + qy * qy + qz * qz;

    float dist[KNN];
    int   idx[KNN];
#pragma unroll
    for (int s = 0; s < KNN; s++) { dist[s] = CUDART_INF_F; idx[s] = 0x7fffffff; }

    __shared__ float4 tile[256];

    for (int t = 0; t < NPTS; t += 256) {
        __syncthreads();
        {
            int cj = t + threadIdx.x;
            float cx = pb[cj * 3 + 0];
            float cy = pb[cj * 3 + 1];
            float cz = pb[cj * 3 + 2];
            tile[threadIdx.x] = make_float4(cx, cy, cz, cx * cx + cy * cy + cz * cz);
        }
        __syncthreads();

#pragma unroll 4
        for (int u = 0; u < 256; u++) {
            int cj = t + u;
            float4 c = tile[u];
            float dot = qx * c.x + qy * c.y + qz * c.z;
            float d2  = qs + c.w - 2.f * dot;
            if (cj == qi) d2 = CUDART_INF_F;   // no self-loop in knn graph
            // insert if better than current worst
            if (d2 < dist[KNN - 1] || (d2 == dist[KNN - 1] && cj < idx[KNN - 1])) {
                float dc = d2; int jc = cj;
#pragma unroll
                for (int s = 0; s < KNN; s++) {
                    bool sw = (dc < dist[s]) || (dc == dist[s] && jc < idx[s]);
                    if (sw) {
                        float td = dist[s]; dist[s] = dc; dc = td;
                        int   ti = idx[s];  idx[s]  = jc; jc = ti;
                    }
                }
            }
        }
    }

    int gi = b * NPTS + qi;
#pragma unroll
    for (int s = 0; s < KNN; s++)
        g_knn[gi * KNN + s] = b * NPTS + idx[s];
}

// ---------------------------------------------------------------------------
// conv1: one warp per node, lane = channel. Lanes 0..16 compute PPF feats of
// their edge (16 knn + self loop), broadcast per edge via shfl, MLP
// 4 -> 32(relu) -> 32, max over edges, final relu.
// ---------------------------------------------------------------------------
__global__ __launch_bounds__(256) void conv1_kernel(
    const float* __restrict__ pos, const float* __restrict__ nrm,
    const float* __restrict__ w1a, const float* __restrict__ b1a,
    const float* __restrict__ w1b, const float* __restrict__ b1b)
{
    int i    = (blockIdx.x * blockDim.x + threadIdx.x) >> 5;
    int lane = threadIdx.x & 31;

    float wa0 = w1a[0 * 32 + lane], wa1 = w1a[1 * 32 + lane];
    float wa2 = w1a[2 * 32 + lane], wa3 = w1a[3 * 32 + lane];
    float ba  = b1a[lane];
    float wb[32];
#pragma unroll
    for (int k = 0; k < 32; k++) wb[k] = w1b[k * 32 + lane];
    float bb = b1b[lane];

    float pix = pos[3 * i + 0], piy = pos[3 * i + 1], piz = pos[3 * i + 2];
    float nix = nrm[3 * i + 0], niy = nrm[3 * i + 1], niz = nrm[3 * i + 2];

    int j = (lane < KNN) ? g_knn[i * KNN + lane] : i;  // lane 16 = self loop
    float pjx = pos[3 * j + 0], pjy = pos[3 * j + 1], pjz = pos[3 * j + 2];
    float njx = nrm[3 * j + 0], njy = nrm[3 * j + 1], njz = nrm[3 * j + 2];

    float px = pjx - pix, py = pjy - piy, pz = pjz - piz;
    float f0 = safe_norm3(px, py, pz);
    float f1 = angle3(nix, niy, niz, px, py, pz);
    float f2 = angle3(njx, njy, njz, px, py, pz);
    float f3 = angle3(nix, niy, niz, njx, njy, njz);

    float best = -CUDART_INF_F;
#pragma unroll
    for (int e = 0; e <= KNN; e++) {
        float e0 = __shfl_sync(0xffffffffu, f0, e);
        float e1 = __shfl_sync(0xffffffffu, f1, e);
        float e2 = __shfl_sync(0xffffffffu, f2, e);
        float e3 = __shfl_sync(0xffffffffu, f3, e);
        float h = ba;
        h = fmaf(e0, wa0, h); h = fmaf(e1, wa1, h);
        h = fmaf(e2, wa2, h); h = fmaf(e3, wa3, h);
        h = fmaxf(h, 0.f);
        float o0 = bb, o1 = 0.f, o2 = 0.f, o3 = 0.f;
#pragma unroll
        for (int k = 0; k < 32; k += 4) {
            o0 = fmaf(__shfl_sync(0xffffffffu, h, k + 0), wb[k + 0], o0);
            o1 = fmaf(__shfl_sync(0xffffffffu, h, k + 1), wb[k + 1], o1);
            o2 = fmaf(__shfl_sync(0xffffffffu, h, k + 2), wb[k + 2], o2);
            o3 = fmaf(__shfl_sync(0xffffffffu, h, k + 3), wb[k + 3], o3);
        }
        best = fmaxf(best, (o0 + o1) + (o2 + o3));
    }
    g_x1[i * CH + lane] = fmaxf(best, 0.f);
}

// ---------------------------------------------------------------------------
// conv2: message = mlp2([x1[src], ppf]) : 36 -> 32(relu) -> 32, scatter max.
// ---------------------------------------------------------------------------
__global__ __launch_bounds__(256) void conv2_kernel(
    const float* __restrict__ pos, const float* __restrict__ nrm,
    const float* __restrict__ w2a, const float* __restrict__ b2a,
    const float* __restrict__ w2b, const float* __restrict__ b2b)
{
    int i    = (blockIdx.x * blockDim.x + threadIdx.x) >> 5;
    int lane = threadIdx.x & 31;

    float wa[36];
#pragma unroll
    for (int k = 0; k < 36; k++) wa[k] = w2a[k * 32 + lane];
    float ba = b2a[lane];
    float wb[32];
#pragma unroll
    for (int k = 0; k < 32; k++) wb[k] = w2b[k * 32 + lane];
    float bb = b2b[lane];

    float pix = pos[3 * i + 0], piy = pos[3 * i + 1], piz = pos[3 * i + 2];
    float nix = nrm[3 * i + 0], niy = nrm[3 * i + 1], niz = nrm[3 * i + 2];

    int j = (lane < KNN) ? g_knn[i * KNN + lane] : i;
    float pjx = pos[3 * j + 0], pjy = pos[3 * j + 1], pjz = pos[3 * j + 2];
    float njx = nrm[3 * j + 0], njy = nrm[3 * j + 1], njz = nrm[3 * j + 2];

    float px = pjx - pix, py = pjy - piy, pz = pjz - piz;
    float f0 = safe_norm3(px, py, pz);
    float f1 = angle3(nix, niy, niz, px, py, pz);
    float f2 = angle3(njx, njy, njz, px, py, pz);
    float f3 = angle3(nix, niy, niz, njx, njy, njz);

    float best = -CUDART_INF_F;
#pragma unroll 1
    for (int e = 0; e <= KNN; e++) {
        int   js = __shfl_sync(0xffffffffu, j, e);
        float xv = g_x1[js * CH + lane];   // lane-coalesced 128B load
        float e0 = __shfl_sync(0xffffffffu, f0, e);
        float e1 = __shfl_sync(0xffffffffu, f1, e);
        float e2 = __shfl_sync(0xffffffffu, f2, e);
        float e3 = __shfl_sync(0xffffffffu, f3, e);

        float h0 = ba, h1 = 0.f;
#pragma unroll
        for (int k = 0; k < 32; k += 2) {
            h0 = fmaf(__shfl_sync(0xffffffffu, xv, k + 0), wa[k + 0], h0);
            h1 = fmaf(__shfl_sync(0xffffffffu, xv, k + 1), wa[k + 1], h1);
        }
        h0 = fmaf(e0, wa[32], h0); h1 = fmaf(e1, wa[33], h1);
        h0 = fmaf(e2, wa[34], h0); h1 = fmaf(e3, wa[35], h1);
        float h = fmaxf(h0 + h1, 0.f);

        float o0 = bb, o1 = 0.f, o2 = 0.f, o3 = 0.f;
#pragma unroll
        for (int k = 0; k < 32; k += 4) {
            o0 = fmaf(__shfl_sync(0xffffffffu, h, k + 0), wb[k + 0], o0);
            o1 = fmaf(__shfl_sync(0xffffffffu, h, k + 1), wb[k + 1], o1);
            o2 = fmaf(__shfl_sync(0xffffffffu, h, k + 2), wb[k + 2], o2);
            o3 = fmaf(__shfl_sync(0xffffffffu, h, k + 3), wb[k + 3], o3);
        }
        best = fmaxf(best, (o0 + o1) + (o2 + o3));
    }
    g_x2[i * CH + lane] = fmaxf(best, 0.f);
}

// ---------------------------------------------------------------------------
// pooling + classifier
// ---------------------------------------------------------------------------
__global__ void pool_init_kernel() {
    int t = threadIdx.x;
    if (t < NB * CH) g_pool[t] = 0.f;
}

__global__ __launch_bounds__(256) void pool_kernel() {
    int lane = threadIdx.x & 31;
    int w    = threadIdx.x >> 5;
    int base = blockIdx.x * 256;      // node base; 256 nodes per block, same batch
    int n0   = base + w * 32;
    float m = 0.f;                    // x2 >= 0
#pragma unroll
    for (int u = 0; u < 32; u++)
        m = fmaxf(m, g_x2[(n0 + u) * CH + lane]);
    __shared__ float sm[8][32];
    sm[w][lane] = m;
    __syncthreads();
    if (threadIdx.x < 32) {
        float g = sm[0][lane];
#pragma unroll
        for (int r = 1; r < 8; r++) g = fmaxf(g, sm[r][lane]);
        int b = base / NPTS;
        // nonneg floats compare correctly as ints
        atomicMax((int*)&g_pool[b * CH + lane], __float_as_int(g));
    }
}

__global__ void fc_kernel(const float* __restrict__ wc,
                          const float* __restrict__ bc,
                          float* __restrict__ out) {
    int t = threadIdx.x;
    if (t < NB * NCLS) {
        int b = t / NCLS, o = t % NCLS;
        float acc = bc[o];
#pragma unroll
        for (int c = 0; c < CH; c++)
            acc = fmaf(g_pool[b * CH + c], wc[c * NCLS + o], acc);
        out[t] = acc;
    }
}

extern "C" void kernel_launch(void* const* d_in, const int* in_sizes, int n_in,
                              void* d_out, int out_size) {
    const float* pos = (const float*)d_in[0];
    const float* nrm = (const float*)d_in[1];
    // d_in[2] = batch (unused; uniform)
    const float* w1a = (const float*)d_in[3];
    const float* b1a = (const float*)d_in[4];
    const float* w1b = (const float*)d_in[5];
    const float* b1b = (const float*)d_in[6];
    const float* w2a = (const float*)d_in[7];
    const float* b2a = (const float*)d_in[8];
    const float* w2b = (const float*)d_in[9];
    const float* b2b = (const float*)d_in[10];
    const float* wc  = (const float*)d_in[11];
    const float* bc  = (const float*)d_in[12];
    float* out = (float*)d_out;

    knn_kernel<<<dim3(NPTS / 256, NB), 256>>>(pos);
    conv1_kernel<<<MPTS / 8, 256>>>(pos, nrm, w1a, b1a, w1b, b1b);
    conv2_kernel<<<MPTS / 8, 256>>>(pos, nrm, w2a, b2a, w2b, b2b);
    pool_init_kernel<<<1, 256>>>();
    pool_kernel<<<MPTS / 256, 256>>>();
    fc_kernel<<<1, 320>>>(wc, bc, out);
}

// round 2
// speedup vs baseline: 3.0029x; 3.0029x over previous
#include <cuda_runtime.h>
#include <math_constants.h>

#define NB 8
#define NPTS 4096
#define KNN 16
#define MPTS (NB * NPTS)
#define CH 32
#define NCLS 40

__device__ float4 g_p4[MPTS];
__device__ int    g_knn[MPTS * KNN];
__device__ float  g_x1[MPTS * CH];
__device__ float  g_x2[MPTS * CH];
__device__ float  g_pool[NB * CH];

__device__ __forceinline__ float safe_norm3(float x, float y, float z) {
    float s = x * x + y * y + z * z;
    return s > 0.f ? sqrtf(s) : 0.f;
}

__device__ __forceinline__ float angle3(float ax, float ay, float az,
                                        float bx, float by, float bz) {
    float cx = ay * bz - az * by;
    float cy = az * bx - ax * bz;
    float cz = ax * by - ay * bx;
    float cn = safe_norm3(cx, cy, cz);
    float d  = ax * bx + ay * by + az * bz;
    bool ok = (cn > 0.f) || (d != 0.f);
    return ok ? atan2f(cn, d) : 0.f;
}

// pack pos -> (x,y,z,|p|^2)
__global__ __launch_bounds__(256) void prep_kernel(const float* __restrict__ pos) {
    int i = blockIdx.x * 256 + threadIdx.x;
    float x = pos[3 * i + 0], y = pos[3 * i + 1], z = pos[3 * i + 2];
    g_p4[i] = make_float4(x, y, z, x * x + y * y + z * z);
}

// ---------------------------------------------------------------------------
// kNN warp-select: 2 queries per warp; each query's top-16 distributed across
// its 16 lanes (sorted ascending by shifted-d2 = |c|^2 - 2 q.c). Strict "<"
// against the running 16th-best + ascending candidate scan == top_k tie-break.
// ---------------------------------------------------------------------------
__global__ __launch_bounds__(256) void knn_kernel() {
    const unsigned FULL = 0xFFFFFFFFu;
    int lane = threadIdx.x & 31;
    int warp = threadIdx.x >> 5;
    int half = lane >> 4;        // which query in the warp
    int lh   = lane & 15;        // rank slot within the query's top-16

    int qbase   = blockIdx.x * 16;            // 16 queries per block
    int q       = qbase + warp * 2 + half;    // global query index
    int batch   = blockIdx.x >> 8;            // 256 blocks per batch
    int q_local = q & (NPTS - 1);

    float4 qp = g_p4[q];
    float m2x = -2.f * qp.x, m2y = -2.f * qp.y, m2z = -2.f * qp.z;

    float L  = CUDART_INF_F;     // my slot's value (shifted d2)
    int   LI = 0;                // my slot's candidate (batch-local idx)
    float tp = CUDART_INF_F;     // running 16th-best (shifted)

    const float4* bp = g_p4 + batch * NPTS;
    __shared__ float4 tile[1024];

    for (int t = 0; t < NPTS; t += 1024) {
        __syncthreads();
#pragma unroll
        for (int u = 0; u < 4; u++)
            tile[threadIdx.x + u * 256] = bp[t + threadIdx.x + u * 256];
        __syncthreads();

#pragma unroll 4
        for (int step = 0; step < 64; step++) {
            int cl = t + step * 16 + lh;                 // batch-local candidate
            float4 c = tile[step * 16 + lh];
            float d = fmaf(c.x, m2x, fmaf(c.y, m2y, fmaf(c.z, m2z, c.w)));
            if (cl == q_local) d = CUDART_INF_F;         // exclude self
            unsigned bal = __ballot_sync(FULL, d < tp);
            while (bal) {
                // one hit from each half per round
                unsigned mb = (bal >> (half << 4)) & 0xFFFFu;
                int srcLane = mb ? ((half << 4) + __ffs(mb) - 1) : 0;
                float v = __shfl_sync(FULL, d, srcLane);
                int  vi = __shfl_sync(FULL, cl, srcLane);
                if (!mb) v = CUDART_INF_F;               // identity insert
                unsigned ble = __ballot_sync(FULL, L <= v);
                int pos = __popc((ble >> (half << 4)) & 0xFFFFu);
                float Lup = __shfl_up_sync(FULL, L, 1);
                int  LIup = __shfl_up_sync(FULL, LI, 1);
                if (lh == pos)      { L = v;   LI = vi;   }
                else if (lh > pos)  { L = Lup; LI = LIup; }
                tp = __shfl_sync(FULL, L, (lane & 16) | 15);
                // strip one processed bit per half (warp-uniform)
                unsigned b0 = bal & 0xFFFFu,      lb0 = b0 & (~b0 + 1u);
                unsigned b1 = bal & 0xFFFF0000u,  lb1 = b1 & (~b1 + 1u);
                bal ^= (lb0 | lb1);
            }
        }
    }
    g_knn[q * KNN + lh] = batch * NPTS + LI;
}

// ---------------------------------------------------------------------------
// conv1: warp per node, lane = channel; edge PPF in lanes 0..16, shfl-bcast.
// ---------------------------------------------------------------------------
__global__ __launch_bounds__(256) void conv1_kernel(
    const float* __restrict__ pos, const float* __restrict__ nrm,
    const float* __restrict__ w1a, const float* __restrict__ b1a,
    const float* __restrict__ w1b, const float* __restrict__ b1b)
{
    const unsigned FULL = 0xFFFFFFFFu;
    int i    = (blockIdx.x * blockDim.x + threadIdx.x) >> 5;
    int lane = threadIdx.x & 31;

    float wa0 = w1a[0 * 32 + lane], wa1 = w1a[1 * 32 + lane];
    float wa2 = w1a[2 * 32 + lane], wa3 = w1a[3 * 32 + lane];
    float ba  = b1a[lane];
    float wb[32];
#pragma unroll
    for (int k = 0; k < 32; k++) wb[k] = w1b[k * 32 + lane];
    float bb = b1b[lane];

    float pix = pos[3 * i + 0], piy = pos[3 * i + 1], piz = pos[3 * i + 2];
    float nix = nrm[3 * i + 0], niy = nrm[3 * i + 1], niz = nrm[3 * i + 2];

    int j = (lane < KNN) ? g_knn[i * KNN + lane] : i;
    float pjx = pos[3 * j + 0], pjy = pos[3 * j + 1], pjz = pos[3 * j + 2];
    float njx = nrm[3 * j + 0], njy = nrm[3 * j + 1], njz = nrm[3 * j + 2];

    float px = pjx - pix, py = pjy - piy, pz = pjz - piz;
    float f0 = safe_norm3(px, py, pz);
    float f1 = angle3(nix, niy, niz, px, py, pz);
    float f2 = angle3(njx, njy, njz, px, py, pz);
    float f3 = angle3(nix, niy, niz, njx, njy, njz);

    float best = -CUDART_INF_F;
#pragma unroll
    for (int e = 0; e <= KNN; e++) {
        float e0 = __shfl_sync(FULL, f0, e);
        float e1 = __shfl_sync(FULL, f1, e);
        float e2 = __shfl_sync(FULL, f2, e);
        float e3 = __shfl_sync(FULL, f3, e);
        float h = ba;
        h = fmaf(e0, wa0, h); h = fmaf(e1, wa1, h);
        h = fmaf(e2, wa2, h); h = fmaf(e3, wa3, h);
        h = fmaxf(h, 0.f);
        float o0 = bb, o1 = 0.f, o2 = 0.f, o3 = 0.f;
#pragma unroll
        for (int k = 0; k < 32; k += 4) {
            o0 = fmaf(__shfl_sync(FULL, h, k + 0), wb[k + 0], o0);
            o1 = fmaf(__shfl_sync(FULL, h, k + 1), wb[k + 1], o1);
            o2 = fmaf(__shfl_sync(FULL, h, k + 2), wb[k + 2], o2);
            o3 = fmaf(__shfl_sync(FULL, h, k + 3), wb[k + 3], o3);
        }
        best = fmaxf(best, (o0 + o1) + (o2 + o3));
    }
    g_x1[i * CH + lane] = fmaxf(best, 0.f);
}

// ---------------------------------------------------------------------------
// conv2: prefetch all 17 x1[src] rows (MLP=17), then shfl-MLP per edge.
// ---------------------------------------------------------------------------
__global__ __launch_bounds__(256) void conv2_kernel(
    const float* __restrict__ pos, const float* __restrict__ nrm,
    const float* __restrict__ w2a, const float* __restrict__ b2a,
    const float* __restrict__ w2b, const float* __restrict__ b2b)
{
    const unsigned FULL = 0xFFFFFFFFu;
    int i    = (blockIdx.x * blockDim.x + threadIdx.x) >> 5;
    int lane = threadIdx.x & 31;

    float wa[36];
#pragma unroll
    for (int k = 0; k < 36; k++) wa[k] = w2a[k * 32 + lane];
    float ba = b2a[lane];
    float wb[32];
#pragma unroll
    for (int k = 0; k < 32; k++) wb[k] = w2b[k * 32 + lane];
    float bb = b2b[lane];

    float pix = pos[3 * i + 0], piy = pos[3 * i + 1], piz = pos[3 * i + 2];
    float nix = nrm[3 * i + 0], niy = nrm[3 * i + 1], niz = nrm[3 * i + 2];

    int j = (lane < KNN) ? g_knn[i * KNN + lane] : i;
    float pjx = pos[3 * j + 0], pjy = pos[3 * j + 1], pjz = pos[3 * j + 2];
    float njx = nrm[3 * j + 0], njy = nrm[3 * j + 1], njz = nrm[3 * j + 2];

    float px = pjx - pix, py = pjy - piy, pz = pjz - piz;
    float f0 = safe_norm3(px, py, pz);
    float f1 = angle3(nix, niy, niz, px, py, pz);
    float f2 = angle3(njx, njy, njz, px, py, pz);
    float f3 = angle3(nix, niy, niz, njx, njy, njz);

    // prefetch neighbor features for all 17 edges (independent loads)
    float xv[KNN + 1];
#pragma unroll
    for (int e = 0; e <= KNN; e++) {
        int js = __shfl_sync(FULL, j, e);
        xv[e] = g_x1[js * CH + lane];
    }

    float best = -CUDART_INF_F;
#pragma unroll
    for (int e = 0; e <= KNN; e++) {
        float e0 = __shfl_sync(FULL, f0, e);
        float e1 = __shfl_sync(FULL, f1, e);
        float e2 = __shfl_sync(FULL, f2, e);
        float e3 = __shfl_sync(FULL, f3, e);

        float h0 = ba, h1 = 0.f;
#pragma unroll
        for (int k = 0; k < 32; k += 2) {
            h0 = fmaf(__shfl_sync(FULL, xv[e], k + 0), wa[k + 0], h0);
            h1 = fmaf(__shfl_sync(FULL, xv[e], k + 1), wa[k + 1], h1);
        }
        h0 = fmaf(e0, wa[32], h0); h1 = fmaf(e1, wa[33], h1);
        h0 = fmaf(e2, wa[34], h0); h1 = fmaf(e3, wa[35], h1);
        float h = fmaxf(h0 + h1, 0.f);

        float o0 = bb, o1 = 0.f, o2 = 0.f, o3 = 0.f;
#pragma unroll
        for (int k = 0; k < 32; k += 4) {
            o0 = fmaf(__shfl_sync(FULL, h, k + 0), wb[k + 0], o0);
            o1 = fmaf(__shfl_sync(FULL, h, k + 1), wb[k + 1], o1);
            o2 = fmaf(__shfl_sync(FULL, h, k + 2), wb[k + 2], o2);
            o3 = fmaf(__shfl_sync(FULL, h, k + 3), wb[k + 3], o3);
        }
        best = fmaxf(best, (o0 + o1) + (o2 + o3));
    }
    g_x2[i * CH + lane] = fmaxf(best, 0.f);
}

// ---------------------------------------------------------------------------
// pooling + classifier
// ---------------------------------------------------------------------------
__global__ void pool_init_kernel() {
    int t = threadIdx.x;
    if (t < NB * CH) g_pool[t] = 0.f;
}

__global__ __launch_bounds__(256) void pool_kernel() {
    int lane = threadIdx.x & 31;
    int w    = threadIdx.x >> 5;
    int base = blockIdx.x * 256;
    int n0   = base + w * 32;
    float m = 0.f;                    // x2 >= 0
#pragma unroll
    for (int u = 0; u < 32; u++)
        m = fmaxf(m, g_x2[(n0 + u) * CH + lane]);
    __shared__ float sm[8][32];
    sm[w][lane] = m;
    __syncthreads();
    if (threadIdx.x < 32) {
        float g = sm[0][lane];
#pragma unroll
        for (int r = 1; r < 8; r++) g = fmaxf(g, sm[r][lane]);
        int b = base / NPTS;
        atomicMax((int*)&g_pool[b * CH + lane], __float_as_int(g));
    }
}

__global__ void fc_kernel(const float* __restrict__ wc,
                          const float* __restrict__ bc,
                          float* __restrict__ out) {
    int t = threadIdx.x;
    if (t < NB * NCLS) {
        int b = t / NCLS, o = t % NCLS;
        float acc = bc[o];
#pragma unroll
        for (int c = 0; c < CH; c++)
            acc = fmaf(g_pool[b * CH + c], wc[c * NCLS + o], acc);
        out[t] = acc;
    }
}

extern "C" void kernel_launch(void* const* d_in, const int* in_sizes, int n_in,
                              void* d_out, int out_size) {
    const float* pos = (const float*)d_in[0];
    const float* nrm = (const float*)d_in[1];
    const float* w1a = (const float*)d_in[3];
    const float* b1a = (const float*)d_in[4];
    const float* w1b = (const float*)d_in[5];
    const float* b1b = (const float*)d_in[6];
    const float* w2a = (const float*)d_in[7];
    const float* b2a = (const float*)d_in[8];
    const float* w2b = (const float*)d_in[9];
    const float* b2b = (const float*)d_in[10];
    const float* wc  = (const float*)d_in[11];
    const float* bc  = (const float*)d_in[12];
    float* out = (float*)d_out;

    prep_kernel<<<MPTS / 256, 256>>>(pos);
    knn_kernel<<<MPTS / 16, 256>>>();
    conv1_kernel<<<MPTS / 8, 256>>>(pos, nrm, w1a, b1a, w1b, b1b);
    conv2_kernel<<<MPTS / 8, 256>>>(pos, nrm, w2a, b2a, w2b, b2b);
    pool_init_kernel<<<1, 256>>>();
    pool_kernel<<<MPTS / 256, 256>>>();
    fc_kernel<<<1, 320>>>(wc, bc, out);
}

// round 3
// speedup vs baseline: 4.1921x; 1.3960x over previous
#include <cuda_runtime.h>
#include <math_constants.h>

#define NB 8
#define NPTS 4096
#define KNN 16
#define MPTS (NB * NPTS)
#define CH 32
#define NCLS 40

__device__ float4 g_p4[MPTS];
__device__ int    g_knn[MPTS * KNN];
__device__ float  g_x1[MPTS * CH];
__device__ float  g_y[MPTS * CH];
__device__ float  g_x2[MPTS * CH];
__device__ float  g_pool[NB * CH];

__device__ __forceinline__ float safe_norm3(float x, float y, float z) {
    float s = x * x + y * y + z * z;
    return s > 0.f ? sqrtf(s) : 0.f;
}

__device__ __forceinline__ float angle3(float ax, float ay, float az,
                                        float bx, float by, float bz) {
    float cx = ay * bz - az * by;
    float cy = az * bx - ax * bz;
    float cz = ax * by - ay * bx;
    float cn = safe_norm3(cx, cy, cz);
    float d  = ax * bx + ay * by + az * bz;
    bool ok = (cn > 0.f) || (d != 0.f);
    return ok ? atan2f(cn, d) : 0.f;
}

__global__ __launch_bounds__(256) void prep_kernel(const float* __restrict__ pos) {
    int i = blockIdx.x * 256 + threadIdx.x;
    float x = pos[3 * i + 0], y = pos[3 * i + 1], z = pos[3 * i + 2];
    g_p4[i] = make_float4(x, y, z, x * x + y * y + z * z);
}

// ---------------------------------------------------------------------------
// kNN warp-select: 2 queries/warp, per-query top-16 distributed over 16 lanes.
// ---------------------------------------------------------------------------
__global__ __launch_bounds__(256) void knn_kernel() {
    const unsigned FULL = 0xFFFFFFFFu;
    int lane = threadIdx.x & 31;
    int warp = threadIdx.x >> 5;
    int half = lane >> 4;
    int lh   = lane & 15;

    int qbase   = blockIdx.x * 16;
    int q       = qbase + warp * 2 + half;
    int batch   = blockIdx.x >> 8;
    int q_local = q & (NPTS - 1);

    float4 qp = g_p4[q];
    float m2x = -2.f * qp.x, m2y = -2.f * qp.y, m2z = -2.f * qp.z;

    float L  = CUDART_INF_F;
    int   LI = 0;
    float tp = CUDART_INF_F;

    const float4* bp = g_p4 + batch * NPTS;
    __shared__ float4 tile[1024];

    for (int t = 0; t < NPTS; t += 1024) {
        __syncthreads();
#pragma unroll
        for (int u = 0; u < 4; u++)
            tile[threadIdx.x + u * 256] = bp[t + threadIdx.x + u * 256];
        __syncthreads();

#pragma unroll 4
        for (int step = 0; step < 64; step++) {
            int cl = t + step * 16 + lh;
            float4 c = tile[step * 16 + lh];
            float d = fmaf(c.x, m2x, fmaf(c.y, m2y, fmaf(c.z, m2z, c.w)));
            if (cl == q_local) d = CUDART_INF_F;
            unsigned bal = __ballot_sync(FULL, d < tp);
            while (bal) {
                unsigned mb = (bal >> (half << 4)) & 0xFFFFu;
                int srcLane = mb ? ((half << 4) + __ffs(mb) - 1) : 0;
                float v = __shfl_sync(FULL, d, srcLane);
                int  vi = __shfl_sync(FULL, cl, srcLane);
                if (!mb) v = CUDART_INF_F;
                unsigned ble = __ballot_sync(FULL, L <= v);
                int pos = __popc((ble >> (half << 4)) & 0xFFFFu);
                float Lup = __shfl_up_sync(FULL, L, 1);
                int  LIup = __shfl_up_sync(FULL, LI, 1);
                if (lh == pos)      { L = v;   LI = vi;   }
                else if (lh > pos)  { L = Lup; LI = LIup; }
                tp = __shfl_sync(FULL, L, (lane & 16) | 15);
                unsigned b0 = bal & 0xFFFFu,      lb0 = b0 & (~b0 + 1u);
                unsigned b1 = bal & 0xFFFF0000u,  lb1 = b1 & (~b1 + 1u);
                bal ^= (lb0 | lb1);
            }
        }
    }
    g_knn[q * KNN + lh] = batch * NPTS + LI;
}

// ---------------------------------------------------------------------------
// conv1: warp per node, lane = channel. Feats + hidden staged in smem; the
// 32-wide broadcasts happen as float4 LDS (4x fewer MIO ops than shfl).
// ---------------------------------------------------------------------------
__global__ __launch_bounds__(256) void conv1_kernel(
    const float* __restrict__ pos, const float* __restrict__ nrm,
    const float* __restrict__ w1a, const float* __restrict__ b1a,
    const float* __restrict__ w1b, const float* __restrict__ b1b)
{
    __shared__ float4 sf[8][20];         // ppf per edge
    __shared__ float  sh[8][17][32];     // hidden per edge
    int warp = threadIdx.x >> 5;
    int lane = threadIdx.x & 31;
    int i    = blockIdx.x * 8 + warp;

    float wa0 = w1a[0 * 32 + lane], wa1 = w1a[1 * 32 + lane];
    float wa2 = w1a[2 * 32 + lane], wa3 = w1a[3 * 32 + lane];
    float ba  = b1a[lane];
    float wb[32];
#pragma unroll
    for (int k = 0; k < 32; k++) wb[k] = w1b[k * 32 + lane];
    float bb = b1b[lane];

    float pix = pos[3 * i + 0], piy = pos[3 * i + 1], piz = pos[3 * i + 2];
    float nix = nrm[3 * i + 0], niy = nrm[3 * i + 1], niz = nrm[3 * i + 2];

    int j = (lane < KNN) ? g_knn[i * KNN + lane] : i;   // lane16 = self loop
    float pjx = pos[3 * j + 0], pjy = pos[3 * j + 1], pjz = pos[3 * j + 2];
    float njx = nrm[3 * j + 0], njy = nrm[3 * j + 1], njz = nrm[3 * j + 2];

    float px = pjx - pix, py = pjy - piy, pz = pjz - piz;
    float f0 = safe_norm3(px, py, pz);
    float f1 = angle3(nix, niy, niz, px, py, pz);
    float f2 = angle3(njx, njy, njz, px, py, pz);
    float f3 = angle3(nix, niy, niz, njx, njy, njz);
    if (lane < 17) sf[warp][lane] = make_float4(f0, f1, f2, f3);
    __syncwarp();

    // layer 1 for all edges
    for (int e = 0; e < 17; e++) {
        float4 f = sf[warp][e];
        float h = ba;
        h = fmaf(f.x, wa0, h); h = fmaf(f.y, wa1, h);
        h = fmaf(f.z, wa2, h); h = fmaf(f.w, wa3, h);
        sh[warp][e][lane] = fmaxf(h, 0.f);
    }
    __syncwarp();

    // layer 2 + max over edges
    float best = -CUDART_INF_F;
    for (int e = 0; e < 17; e++) {
        float o0 = bb, o1 = 0.f, o2 = 0.f, o3 = 0.f;
        const float4* hv4 = (const float4*)sh[warp][e];
#pragma unroll
        for (int m = 0; m < 8; m++) {
            float4 hv = hv4[m];
            o0 = fmaf(hv.x, wb[4 * m + 0], o0);
            o1 = fmaf(hv.y, wb[4 * m + 1], o1);
            o2 = fmaf(hv.z, wb[4 * m + 2], o2);
            o3 = fmaf(hv.w, wb[4 * m + 3], o3);
        }
        best = fmaxf(best, (o0 + o1) + (o2 + o3));
    }
    g_x1[i * CH + lane] = fmaxf(best, 0.f);
}

// ---------------------------------------------------------------------------
// y = x1 @ w2a[0:32] + b2a  (per node — hoists the edge-invariant sub-GEMM)
// ---------------------------------------------------------------------------
__global__ __launch_bounds__(256) void y_kernel(
    const float* __restrict__ w2a, const float* __restrict__ b2a)
{
    __shared__ float sx[8][32];
    int warp = threadIdx.x >> 5;
    int lane = threadIdx.x & 31;
    int i    = blockIdx.x * 8 + warp;

    float w2[32];
#pragma unroll
    for (int k = 0; k < 32; k++) w2[k] = w2a[k * 32 + lane];

    sx[warp][lane] = g_x1[i * CH + lane];
    __syncwarp();

    float a0 = b2a[lane], a1 = 0.f, a2 = 0.f, a3 = 0.f;
    const float4* xv4 = (const float4*)sx[warp];
#pragma unroll
    for (int m = 0; m < 8; m++) {
        float4 xv = xv4[m];
        a0 = fmaf(xv.x, w2[4 * m + 0], a0);
        a1 = fmaf(xv.y, w2[4 * m + 1], a1);
        a2 = fmaf(xv.z, w2[4 * m + 2], a2);
        a3 = fmaf(xv.w, w2[4 * m + 3], a3);
    }
    g_y[i * CH + lane] = (a0 + a1) + (a2 + a3);
}

// ---------------------------------------------------------------------------
// conv2: h = relu(y[src] + w2a[32:36]^T f); out = h @ w2b; max over edges.
// ---------------------------------------------------------------------------
__global__ __launch_bounds__(256) void conv2_kernel(
    const float* __restrict__ pos, const float* __restrict__ nrm,
    const float* __restrict__ w2a, const float* __restrict__ b2a,
    const float* __restrict__ w2b, const float* __restrict__ b2b)
{
    __shared__ float4 sf[8][20];
    __shared__ int    si[8][20];
    __shared__ float  sh[8][17][32];
    int warp = threadIdx.x >> 5;
    int lane = threadIdx.x & 31;
    int i    = blockIdx.x * 8 + warp;

    float wa32 = w2a[32 * 32 + lane], wa33 = w2a[33 * 32 + lane];
    float wa34 = w2a[34 * 32 + lane], wa35 = w2a[35 * 32 + lane];
    float wb[32];
#pragma unroll
    for (int k = 0; k < 32; k++) wb[k] = w2b[k * 32 + lane];
    float bb = b2b[lane];

    float pix = pos[3 * i + 0], piy = pos[3 * i + 1], piz = pos[3 * i + 2];
    float nix = nrm[3 * i + 0], niy = nrm[3 * i + 1], niz = nrm[3 * i + 2];

    int j = (lane < KNN) ? g_knn[i * KNN + lane] : i;
    float pjx = pos[3 * j + 0], pjy = pos[3 * j + 1], pjz = pos[3 * j + 2];
    float njx = nrm[3 * j + 0], njy = nrm[3 * j + 1], njz = nrm[3 * j + 2];

    float px = pjx - pix, py = pjy - piy, pz = pjz - piz;
    float f0 = safe_norm3(px, py, pz);
    float f1 = angle3(nix, niy, niz, px, py, pz);
    float f2 = angle3(njx, njy, njz, px, py, pz);
    float f3 = angle3(nix, niy, niz, njx, njy, njz);
    if (lane < 17) { sf[warp][lane] = make_float4(f0, f1, f2, f3); si[warp][lane] = j; }
    __syncwarp();

    // prefetch y rows (coalesced, independent)
    float yv[17];
#pragma unroll
    for (int e = 0; e < 17; e++)
        yv[e] = g_y[si[warp][e] * CH + lane];

    // layer 1
#pragma unroll
    for (int e = 0; e < 17; e++) {
        float4 f = sf[warp][e];
        float h = yv[e];
        h = fmaf(f.x, wa32, h); h = fmaf(f.y, wa33, h);
        h = fmaf(f.z, wa34, h); h = fmaf(f.w, wa35, h);
        sh[warp][e][lane] = fmaxf(h, 0.f);
    }
    __syncwarp();

    // layer 2 + max
    float best = -CUDART_INF_F;
    for (int e = 0; e < 17; e++) {
        float o0 = bb, o1 = 0.f, o2 = 0.f, o3 = 0.f;
        const float4* hv4 = (const float4*)sh[warp][e];
#pragma unroll
        for (int m = 0; m < 8; m++) {
            float4 hv = hv4[m];
            o0 = fmaf(hv.x, wb[4 * m + 0], o0);
            o1 = fmaf(hv.y, wb[4 * m + 1], o1);
            o2 = fmaf(hv.z, wb[4 * m + 2], o2);
            o3 = fmaf(hv.w, wb[4 * m + 3], o3);
        }
        best = fmaxf(best, (o0 + o1) + (o2 + o3));
    }
    g_x2[i * CH + lane] = fmaxf(best, 0.f);
}

// ---------------------------------------------------------------------------
// pooling + classifier
// ---------------------------------------------------------------------------
__global__ void pool_init_kernel() {
    int t = threadIdx.x;
    if (t < NB * CH) g_pool[t] = 0.f;
}

__global__ __launch_bounds__(256) void pool_kernel() {
    int lane = threadIdx.x & 31;
    int w    = threadIdx.x >> 5;
    int base = blockIdx.x * 256;
    int n0   = base + w * 32;
    float m = 0.f;
#pragma unroll
    for (int u = 0; u < 32; u++)
        m = fmaxf(m, g_x2[(n0 + u) * CH + lane]);
    __shared__ float sm[8][32];
    sm[w][lane] = m;
    __syncthreads();
    if (threadIdx.x < 32) {
        float g = sm[0][lane];
#pragma unroll
        for (int r = 1; r < 8; r++) g = fmaxf(g, sm[r][lane]);
        int b = base / NPTS;
        atomicMax((int*)&g_pool[b * CH + lane], __float_as_int(g));
    }
}

__global__ void fc_kernel(const float* __restrict__ wc,
                          const float* __restrict__ bc,
                          float* __restrict__ out) {
    int t = threadIdx.x;
    if (t < NB * NCLS) {
        int b = t / NCLS, o = t % NCLS;
        float acc = bc[o];
#pragma unroll
        for (int c = 0; c < CH; c++)
            acc = fmaf(g_pool[b * CH + c], wc[c * NCLS + o], acc);
        out[t] = acc;
    }
}

extern "C" void kernel_launch(void* const* d_in, const int* in_sizes, int n_in,
                              void* d_out, int out_size) {
    const float* pos = (const float*)d_in[0];
    const float* nrm = (const float*)d_in[1];
    const float* w1a = (const float*)d_in[3];
    const float* b1a = (const float*)d_in[4];
    const float* w1b = (const float*)d_in[5];
    const float* b1b = (const float*)d_in[6];
    const float* w2a = (const float*)d_in[7];
    const float* b2a = (const float*)d_in[8];
    const float* w2b = (const float*)d_in[9];
    const float* b2b = (const float*)d_in[10];
    const float* wc  = (const float*)d_in[11];
    const float* bc  = (const float*)d_in[12];
    float* out = (float*)d_out;

    prep_kernel<<<MPTS / 256, 256>>>(pos);
    knn_kernel<<<MPTS / 16, 256>>>();
    conv1_kernel<<<MPTS / 8, 256>>>(pos, nrm, w1a, b1a, w1b, b1b);
    y_kernel<<<MPTS / 8, 256>>>(w2a, b2a);
    conv2_kernel<<<MPTS / 8, 256>>>(pos, nrm, w2a, b2a, w2b, b2b);
    pool_init_kernel<<<1, 256>>>();
    pool_kernel<<<MPTS / 256, 256>>>();
    fc_kernel<<<1, 320>>>(wc, bc, out);
}

// round 4
// speedup vs baseline: 4.2495x; 1.0137x over previous
#include <cuda_runtime.h>
#include <math_constants.h>

#define NB 8
#define NPTS 4096
#define KNN 16
#define MPTS (NB * NPTS)
#define CH 32
#define NCLS 40

__device__ float4 g_p4[MPTS];
__device__ int    g_knn[MPTS * KNN];
__device__ float  g_y[MPTS * CH];
__device__ float  g_pool[NB * CH];

__device__ __forceinline__ float safe_norm3(float x, float y, float z) {
    float s = x * x + y * y + z * z;
    return s > 0.f ? sqrtf(s) : 0.f;
}

__device__ __forceinline__ float angle3(float ax, float ay, float az,
                                        float bx, float by, float bz) {
    float cx = ay * bz - az * by;
    float cy = az * bx - ax * bz;
    float cz = ax * by - ay * bx;
    float cn = safe_norm3(cx, cy, cz);
    float d  = ax * bx + ay * by + az * bz;
    bool ok = (cn > 0.f) || (d != 0.f);
    return ok ? atan2f(cn, d) : 0.f;
}

// pos -> (x,y,z,|p|^2), split in two so knn lands on ncu's 4th-launch sample
__global__ __launch_bounds__(256) void prep_kernel(const float* __restrict__ pos,
                                                   int base) {
    int i = base + blockIdx.x * 256 + threadIdx.x;
    float x = pos[3 * i + 0], y = pos[3 * i + 1], z = pos[3 * i + 2];
    g_p4[i] = make_float4(x, y, z, x * x + y * y + z * z);
}

__global__ void pool_init_kernel() {
    int t = threadIdx.x;
    if (t < NB * CH) g_pool[t] = 0.f;
}

// ---------------------------------------------------------------------------
// kNN warp-select: 2 queries/warp, per-query top-16 distributed over 16 lanes.
// ---------------------------------------------------------------------------
__global__ __launch_bounds__(256) void knn_kernel() {
    const unsigned FULL = 0xFFFFFFFFu;
    int lane = threadIdx.x & 31;
    int warp = threadIdx.x >> 5;
    int half = lane >> 4;
    int lh   = lane & 15;

    int qbase   = blockIdx.x * 16;
    int q       = qbase + warp * 2 + half;
    int batch   = blockIdx.x >> 8;
    int q_local = q & (NPTS - 1);

    float4 qp = g_p4[q];
    float m2x = -2.f * qp.x, m2y = -2.f * qp.y, m2z = -2.f * qp.z;

    float L  = CUDART_INF_F;
    int   LI = 0;
    float tp = CUDART_INF_F;

    const float4* bp = g_p4 + batch * NPTS;
    __shared__ float4 tile[1024];

    for (int t = 0; t < NPTS; t += 1024) {
        __syncthreads();
#pragma unroll
        for (int u = 0; u < 4; u++)
            tile[threadIdx.x + u * 256] = bp[t + threadIdx.x + u * 256];
        __syncthreads();

#pragma unroll 4
        for (int step = 0; step < 64; step++) {
            int cl = t + step * 16 + lh;
            float4 c = tile[step * 16 + lh];
            float d = fmaf(c.x, m2x, fmaf(c.y, m2y, fmaf(c.z, m2z, c.w)));
            if (cl == q_local) d = CUDART_INF_F;
            unsigned bal = __ballot_sync(FULL, d < tp);
            while (bal) {
                unsigned mb = (bal >> (half << 4)) & 0xFFFFu;
                int srcLane = mb ? ((half << 4) + __ffs(mb) - 1) : 0;
                float v = __shfl_sync(FULL, d, srcLane);
                int  vi = __shfl_sync(FULL, cl, srcLane);
                if (!mb) v = CUDART_INF_F;
                unsigned ble = __ballot_sync(FULL, L <= v);
                int pos = __popc((ble >> (half << 4)) & 0xFFFFu);
                float Lup = __shfl_up_sync(FULL, L, 1);
                int  LIup = __shfl_up_sync(FULL, LI, 1);
                if (lh == pos)      { L = v;   LI = vi;   }
                else if (lh > pos)  { L = Lup; LI = LIup; }
                tp = __shfl_sync(FULL, L, (lane & 16) | 15);
                unsigned b0 = bal & 0xFFFFu,      lb0 = b0 & (~b0 + 1u);
                unsigned b1 = bal & 0xFFFF0000u,  lb1 = b1 & (~b1 + 1u);
                bal ^= (lb0 | lb1);
            }
        }
    }
    g_knn[q * KNN + lh] = batch * NPTS + LI;
}

// ---------------------------------------------------------------------------
// conv1 (+ fused y): warp per node, lane = channel. Computes x1 then directly
// y = w2a[0:32]^T x1 + b2a, never materializing x1 in global memory.
// ---------------------------------------------------------------------------
__global__ __launch_bounds__(256) void conv1_kernel(
    const float* __restrict__ pos, const float* __restrict__ nrm,
    const float* __restrict__ w1a, const float* __restrict__ b1a,
    const float* __restrict__ w1b, const float* __restrict__ b1b,
    const float* __restrict__ w2a, const float* __restrict__ b2a)
{
    __shared__ float4 sf[8][20];         // ppf per edge
    __shared__ float  sh[8][17][32];     // hidden per edge
    int warp = threadIdx.x >> 5;
    int lane = threadIdx.x & 31;
    int i    = blockIdx.x * 8 + warp;

    float wa0 = w1a[0 * 32 + lane], wa1 = w1a[1 * 32 + lane];
    float wa2 = w1a[2 * 32 + lane], wa3 = w1a[3 * 32 + lane];
    float ba  = b1a[lane];
    float wb[32];
#pragma unroll
    for (int k = 0; k < 32; k++) wb[k] = w1b[k * 32 + lane];
    float bb = b1b[lane];

    float pix = pos[3 * i + 0], piy = pos[3 * i + 1], piz = pos[3 * i + 2];
    float nix = nrm[3 * i + 0], niy = nrm[3 * i + 1], niz = nrm[3 * i + 2];

    int j = (lane < KNN) ? g_knn[i * KNN + lane] : i;   // lane16 = self loop
    float pjx = pos[3 * j + 0], pjy = pos[3 * j + 1], pjz = pos[3 * j + 2];
    float njx = nrm[3 * j + 0], njy = nrm[3 * j + 1], njz = nrm[3 * j + 2];

    float px = pjx - pix, py = pjy - piy, pz = pjz - piz;
    float f0 = safe_norm3(px, py, pz);
    float f1 = angle3(nix, niy, niz, px, py, pz);
    float f2 = angle3(njx, njy, njz, px, py, pz);
    float f3 = angle3(nix, niy, niz, njx, njy, njz);
    if (lane < 17) sf[warp][lane] = make_float4(f0, f1, f2, f3);
    __syncwarp();

    for (int e = 0; e < 17; e++) {
        float4 f = sf[warp][e];
        float h = ba;
        h = fmaf(f.x, wa0, h); h = fmaf(f.y, wa1, h);
        h = fmaf(f.z, wa2, h); h = fmaf(f.w, wa3, h);
        sh[warp][e][lane] = fmaxf(h, 0.f);
    }
    __syncwarp();

    float best = -CUDART_INF_F;
    for (int e = 0; e < 17; e++) {
        float o0 = bb, o1 = 0.f, o2 = 0.f, o3 = 0.f;
        const float4* hv4 = (const float4*)sh[warp][e];
#pragma unroll
        for (int m = 0; m < 8; m++) {
            float4 hv = hv4[m];
            o0 = fmaf(hv.x, wb[4 * m + 0], o0);
            o1 = fmaf(hv.y, wb[4 * m + 1], o1);
            o2 = fmaf(hv.z, wb[4 * m + 2], o2);
            o3 = fmaf(hv.w, wb[4 * m + 3], o3);
        }
        best = fmaxf(best, (o0 + o1) + (o2 + o3));
    }
    float x1v = fmaxf(best, 0.f);

    // fused y = w2a[0:32]^T x1 + b2a
    sh[warp][0][lane] = x1v;
    __syncwarp();
    float w2[32];
#pragma unroll
    for (int k = 0; k < 32; k++) w2[k] = w2a[k * 32 + lane];
    float a0 = b2a[lane], a1 = 0.f, a2 = 0.f, a3 = 0.f;
    const float4* xv4 = (const float4*)sh[warp][0];
#pragma unroll
    for (int m = 0; m < 8; m++) {
        float4 xv = xv4[m];
        a0 = fmaf(xv.x, w2[4 * m + 0], a0);
        a1 = fmaf(xv.y, w2[4 * m + 1], a1);
        a2 = fmaf(xv.z, w2[4 * m + 2], a2);
        a3 = fmaf(xv.w, w2[4 * m + 3], a3);
    }
    g_y[i * CH + lane] = (a0 + a1) + (a2 + a3);
}

// ---------------------------------------------------------------------------
// conv2 (+ fused global max pool): h = relu(y[src] + w2a[32:36]^T f);
// out = h @ w2b + b2b; relu; block-reduce max; one atomicMax per block/lane.
// ---------------------------------------------------------------------------
__global__ __launch_bounds__(256) void conv2_kernel(
    const float* __restrict__ pos, const float* __restrict__ nrm,
    const float* __restrict__ w2a,
    const float* __restrict__ w2b, const float* __restrict__ b2b)
{
    __shared__ float4 sf[8][20];
    __shared__ int    si[8][20];
    __shared__ float  sh[8][17][32];
    __shared__ float  red[8][32];
    int warp = threadIdx.x >> 5;
    int lane = threadIdx.x & 31;
    int i    = blockIdx.x * 8 + warp;

    float wa32 = w2a[32 * 32 + lane], wa33 = w2a[33 * 32 + lane];
    float wa34 = w2a[34 * 32 + lane], wa35 = w2a[35 * 32 + lane];
    float wb[32];
#pragma unroll
    for (int k = 0; k < 32; k++) wb[k] = w2b[k * 32 + lane];
    float bb = b2b[lane];

    float pix = pos[3 * i + 0], piy = pos[3 * i + 1], piz = pos[3 * i + 2];
    float nix = nrm[3 * i + 0], niy = nrm[3 * i + 1], niz = nrm[3 * i + 2];

    int j = (lane < KNN) ? g_knn[i * KNN + lane] : i;
    float pjx = pos[3 * j + 0], pjy = pos[3 * j + 1], pjz = pos[3 * j + 2];
    float njx = nrm[3 * j + 0], njy = nrm[3 * j + 1], njz = nrm[3 * j + 2];

    float px = pjx - pix, py = pjy - piy, pz = pjz - piz;
    float f0 = safe_norm3(px, py, pz);
    float f1 = angle3(nix, niy, niz, px, py, pz);
    float f2 = angle3(njx, njy, njz, px, py, pz);
    float f3 = angle3(nix, niy, niz, njx, njy, njz);
    if (lane < 17) { sf[warp][lane] = make_float4(f0, f1, f2, f3); si[warp][lane] = j; }
    __syncwarp();

    float yv[17];
#pragma unroll
    for (int e = 0; e < 17; e++)
        yv[e] = g_y[si[warp][e] * CH + lane];

#pragma unroll
    for (int e = 0; e < 17; e++) {
        float4 f = sf[warp][e];
        float h = yv[e];
        h = fmaf(f.x, wa32, h); h = fmaf(f.y, wa33, h);
        h = fmaf(f.z, wa34, h); h = fmaf(f.w, wa35, h);
        sh[warp][e][lane] = fmaxf(h, 0.f);
    }
    __syncwarp();

    float best = -CUDART_INF_F;
    for (int e = 0; e < 17; e++) {
        float o0 = bb, o1 = 0.f, o2 = 0.f, o3 = 0.f;
        const float4* hv4 = (const float4*)sh[warp][e];
#pragma unroll
        for (int m = 0; m < 8; m++) {
            float4 hv = hv4[m];
            o0 = fmaf(hv.x, wb[4 * m + 0], o0);
            o1 = fmaf(hv.y, wb[4 * m + 1], o1);
            o2 = fmaf(hv.z, wb[4 * m + 2], o2);
            o3 = fmaf(hv.w, wb[4 * m + 3], o3);
        }
        best = fmaxf(best, (o0 + o1) + (o2 + o3));
    }
    red[warp][lane] = fmaxf(best, 0.f);    // x2 >= 0
    __syncthreads();

    if (warp == 0) {
        float m = red[0][lane];
#pragma unroll
        for (int r = 1; r < 8; r++) m = fmaxf(m, red[r][lane]);
        int b = (blockIdx.x * 8) >> 12;    // 4096 nodes per batch
        atomicMax((int*)&g_pool[b * CH + lane], __float_as_int(m));
    }
}

__global__ void fc_kernel(const float* __restrict__ wc,
                          const float* __restrict__ bc,
                          float* __restrict__ out) {
    int t = threadIdx.x;
    if (t < NB * NCLS) {
        int b = t / NCLS, o = t % NCLS;
        float acc = bc[o];
#pragma unroll
        for (int c = 0; c < CH; c++)
            acc = fmaf(g_pool[b * CH + c], wc[c * NCLS + o], acc);
        out[t] = acc;
    }
}

extern "C" void kernel_launch(void* const* d_in, const int* in_sizes, int n_in,
                              void* d_out, int out_size) {
    const float* pos = (const float*)d_in[0];
    const float* nrm = (const float*)d_in[1];
    const float* w1a = (const float*)d_in[3];
    const float* b1a = (const float*)d_in[4];
    const float* w1b = (const float*)d_in[5];
    const float* b1b = (const float*)d_in[6];
    const float* w2a = (const float*)d_in[7];
    const float* b2a = (const float*)d_in[8];
    const float* w2b = (const float*)d_in[9];
    const float* b2b = (const float*)d_in[10];
    const float* wc  = (const float*)d_in[11];
    const float* bc  = (const float*)d_in[12];
    float* out = (float*)d_out;

    prep_kernel<<<MPTS / 512, 256>>>(pos, 0);            // launch 1
    prep_kernel<<<MPTS / 512, 256>>>(pos, MPTS / 2);     // launch 2
    pool_init_kernel<<<1, 256>>>();                      // launch 3
    knn_kernel<<<MPTS / 16, 256>>>();                    // launch 4 (ncu sample)
    conv1_kernel<<<MPTS / 8, 256>>>(pos, nrm, w1a, b1a, w1b, b1b, w2a, b2a);
    conv2_kernel<<<MPTS / 8, 256>>>(pos, nrm, w2a, w2b, b2b);
    fc_kernel<<<1, 320>>>(wc, bc, out);
}